// round 8
// baseline (speedup 1.0000x reference)
#include <cuda_runtime.h>
#include <cuda_bf16.h>

// EISANI sparse ternary net. B=512, F=128, NUM_BITS=16, E=2048, H=8192, C=10.
// R6: Harley-Seal bit-sliced layers (CSA planes, no serial ripple), paired u32
// entry layout, pad-to-8; extraction MLP=8 with integer sign tests; deeper
// stream overlap (layer1/outparts hidden under extract W2).

#define HID 8192
#define ENC 2048
#define BATCH 512
#define NGRP 16
#define CAP 96
#define CLASSES 10
#define OCH 128
#define NCHUNK 192          // 3 * HID / OCH

// entry slot j of row h lives at u16 address ((j>>1)*2*HID + 2*h + (j&1));
// u32 view index (j>>1)*HID + h holds entries j (lo) and j+1 (hi).
#define ESLOT(j, h) ((((j) >> 1) * 2 * HID) + 2 * (h) + ((j) & 1))

// ---------------- scratch ----------------
__device__ unsigned short g_ent0[CAP * HID];
__device__ unsigned short g_ent1[CAP * HID];
__device__ unsigned short g_ent2[CAP * HID];
__device__ int g_cnt[6 * HID];      // pc0,nc0,pc1,nc1,pc2,nc2 (zeroed by outfinal)
__device__ int g_cp0[HID], g_ns0[HID];
__device__ int g_cp1[HID], g_ns1[HID];
__device__ int g_cp2[HID], g_ns2[HID];
__device__ unsigned g_act0[NGRP * ENC];
__device__ unsigned g_act1[NGRP * HID];
__device__ unsigned g_act2[NGRP * HID];
__device__ unsigned g_act3[NGRP * HID];
__device__ float    g_part[NCHUNK * BATCH * CLASSES];
__device__ float    g_sink[BATCH * CLASSES + BATCH];

// ---------------- 1) extraction: streaming MLP=8, atomic append -------------
__global__ __launch_bounds__(256) void extract_kernel(
    const float4* __restrict__ W, int f4shf, int total_f4,
    unsigned short* __restrict__ entT, int* __restrict__ pc, int* __restrict__ nc)
{
    int t  = blockIdx.x * blockDim.x + threadIdx.x;
    int NT = gridDim.x * blockDim.x;
    int f4mask = (1 << f4shf) - 1;

    for (int base = 0; base < total_f4; base += NT * 8) {
        float4 v[8];
        int idx[8];
        #pragma unroll
        for (int j = 0; j < 8; j++) {
            idx[j] = base + t + j * NT;
            if (idx[j] < total_f4) v[j] = __ldcs(W + idx[j]);
            else                   v[j] = make_float4(0.f, 0.f, 0.f, 0.f);
        }
        #pragma unroll
        for (int j = 0; j < 8; j++) {
            int u0 = __float_as_int(v[j].x), u1 = __float_as_int(v[j].y);
            int u2 = __float_as_int(v[j].z), u3 = __float_as_int(v[j].w);
            unsigned ored = ((unsigned)(u0 | u1 | u2 | u3)) << 1;
            if (ored == 0u) continue;          // all four exactly zero
            int sp0 = (u0 > 0), sp1 = (u1 > 0), sp2 = (u2 > 0), sp3 = (u3 > 0);
            int sn0 = (u0 < 0), sn1 = (u1 < 0), sn2 = (u2 < 0), sn3 = (u3 < 0);
            int cntp = sp0 + sp1 + sp2 + sp3;
            int cntn = sn0 + sn1 + sn2 + sn3;
            int row  = idx[j] >> f4shf;
            int col4 = (idx[j] & f4mask) << 2;
            if (cntp) {
                int bp = atomicAdd(&pc[row], cntp);
                int sp[4] = {sp0, sp1, sp2, sp3};
                #pragma unroll
                for (int k = 0; k < 4; k++) {
                    if (sp[k]) {
                        if (bp < CAP) entT[ESLOT(bp, row)] = (unsigned short)(col4 + k);
                        bp++;
                    }
                }
            }
            if (cntn) {
                int bn = atomicAdd(&nc[row], cntn);
                int sn[4] = {sn0, sn1, sn2, sn3};
                #pragma unroll
                for (int k = 0; k < 4; k++) {
                    if (sn[k]) {
                        int sl = CAP - 1 - bn;
                        if (sl >= 0) entT[ESLOT(sl, row)] = (unsigned short)(col4 + k);
                        bn++;
                    }
                }
            }
        }
    }
}

// ---------------- pad: round counts to mult of 8 with sentinels -------------
__device__ __forceinline__ void pad_row(int row, const int* pc, const int* nc,
                                        int P, unsigned short* entT,
                                        int* cp8, int* ns8)
{
    int cp = min(pc[row], 48);
    int cn = min(nc[row], 48);
    int cpp = (cp + 7) & ~7;
    for (int j = cp; j < cpp; j++) entT[ESLOT(j, row)] = (unsigned short)P;
    int ns  = CAP - cn;
    int nsp = ns & ~7;
    for (int j = nsp; j < ns; j++) entT[ESLOT(j, row)] = (unsigned short)P;
    cp8[row] = cpp;
    ns8[row] = nsp;
}

__global__ void pad_kernel(const int* __restrict__ pc, const int* __restrict__ nc,
                           int P, unsigned short* __restrict__ entT,
                           int* __restrict__ cp8, int* __restrict__ ns8)
{
    int row = blockIdx.x * blockDim.x + threadIdx.x;
    if (row < HID) pad_row(row, pc, nc, P, entT, cp8, ns8);
}

// ---------------- 2) thermometer encode ----------------
__global__ __launch_bounds__(256) void encode_kernel(
    const float* __restrict__ x, unsigned* __restrict__ act0T)
{
    __shared__ float xs[32 * 129];
    int g = blockIdx.x;
    int tid = threadIdx.x;
    const float* xg = x + (size_t)g * 32 * 128;
    for (int i = tid; i < 4096; i += 256)
        xs[(i >> 7) * 129 + (i & 127)] = xg[i];
    __syncthreads();
    int w = tid >> 5, lane = tid & 31;
    for (int f = w; f < 128; f += 8) {
        float xv = xs[lane * 129 + f] * 16.0f;
        unsigned myword = 0;
        #pragma unroll
        for (int j = 0; j < 16; j++) {
            unsigned m = __ballot_sync(0xFFFFFFFFu, xv > (float)j);
            if (lane == j) myword = m;
        }
        if (lane < 16) act0T[g * ENC + f * 16 + lane] = myword;
    }
}

// ---------------- 3) bit-sliced layer (Harley-Seal CSA planes) --------------
__device__ __forceinline__ void csa(unsigned& c, unsigned& s, unsigned a, unsigned b)
{
    unsigned t = s ^ a;
    c = (s & a) | (t & b);
    s = t ^ b;
}

__device__ __forceinline__ void hs8(unsigned (&pl)[6],
    unsigned v0, unsigned v1, unsigned v2, unsigned v3,
    unsigned v4, unsigned v5, unsigned v6, unsigned v7)
{
    unsigned a1, a2, a3, a4, b1, b2, c1;
    csa(a1, pl[0], v0, v1);
    csa(a2, pl[0], v2, v3);
    csa(a3, pl[0], v4, v5);
    csa(a4, pl[0], v6, v7);
    csa(b1, pl[1], a1, a2);
    csa(b2, pl[1], a3, a4);
    csa(c1, pl[2], b1, b2);
    unsigned t0 = pl[3] & c1; pl[3] ^= c1;
    unsigned t1 = pl[4] & t0; pl[4] ^= t0;
    pl[5] ^= t1;
}

template <int KDIM>
__global__ __launch_bounds__(256) void layer_kernel(
    const unsigned* __restrict__ entP,      // paired u32 view
    const int* __restrict__ cp8, const int* __restrict__ ns8,
    const unsigned* __restrict__ actInT,
    unsigned* __restrict__ actOutT)
{
    __shared__ unsigned slice[KDIM + 4];
    int tid = threadIdx.x;
    int h = blockIdx.x * 256 + tid;
    int g = blockIdx.y;
    const uint4* src4 = reinterpret_cast<const uint4*>(actInT + (size_t)g * KDIM);
    uint4* dst4 = reinterpret_cast<uint4*>(slice);
    for (int i = tid; i < KDIM / 4; i += 256) dst4[i] = src4[i];
    if (tid == 0) slice[KDIM] = 0u;    // sentinel for padded entries
    __syncthreads();

    int cp = cp8[h];
    int ns = ns8[h];
    unsigned p[6] = {0, 0, 0, 0, 0, 0};
    unsigned n[6] = {0, 0, 0, 0, 0, 0};
    const unsigned* ep = entP + h;

    #pragma unroll 1
    for (int j = 0; j < cp; j += 8) {
        int jj = j >> 1;
        unsigned e0 = ep[(jj + 0) * HID], e1 = ep[(jj + 1) * HID];
        unsigned e2 = ep[(jj + 2) * HID], e3 = ep[(jj + 3) * HID];
        hs8(p, slice[e0 & 0xFFFF], slice[e0 >> 16],
               slice[e1 & 0xFFFF], slice[e1 >> 16],
               slice[e2 & 0xFFFF], slice[e2 >> 16],
               slice[e3 & 0xFFFF], slice[e3 >> 16]);
    }
    #pragma unroll 1
    for (int j = ns; j < CAP; j += 8) {
        int jj = j >> 1;
        unsigned e0 = ep[(jj + 0) * HID], e1 = ep[(jj + 1) * HID];
        unsigned e2 = ep[(jj + 2) * HID], e3 = ep[(jj + 3) * HID];
        hs8(n, slice[e0 & 0xFFFF], slice[e0 >> 16],
               slice[e1 & 0xFFFF], slice[e1 >> 16],
               slice[e2 & 0xFFFF], slice[e2 >> 16],
               slice[e3 & 0xFFFF], slice[e3 >> 16]);
    }

    // S = P + ~N (6-bit); z = P - N >= 4 <=> S >= 67 (1000011b)
    unsigned s[7], carry = 0;
    #pragma unroll
    for (int i = 0; i < 6; i++) {
        unsigned q = ~n[i];
        unsigned x1 = p[i] ^ q;
        s[i] = x1 ^ carry;
        carry = (p[i] & q) | (carry & x1);
    }
    s[6] = carry;
    unsigned gt = 0, eq = 0xFFFFFFFFu;
    eq &= s[6];
    #pragma unroll
    for (int i = 5; i >= 2; i--) { gt |= eq & s[i]; eq &= ~s[i]; }
    eq &= s[1];
    eq &= s[0];
    actOutT[(size_t)g * HID + h] = gt | eq;
}

// ---------------- 4a) output partials (per layer) ----------------
__global__ __launch_bounds__(256) void outpart_kernel(
    const unsigned* __restrict__ act, const float* __restrict__ ocLayer,
    float* __restrict__ partLayer)
{
    __shared__ float    ocs[OCH * CLASSES];
    __shared__ unsigned ws[OCH * 8];
    int chunk = blockIdx.x;                 // 0..63
    int half  = blockIdx.y;                 // 0..1
    int hbase = chunk * OCH;
    const float* oc = ocLayer + (size_t)hbase * CLASSES;
    int tid = threadIdx.x;
    for (int i = tid; i < OCH * CLASSES; i += 256) ocs[i] = oc[i];
    for (int i = tid; i < OCH * 8; i += 256) {
        int hh = i >> 3, gl = i & 7;
        ws[i] = act[(size_t)(half * 8 + gl) * HID + hbase + hh];
    }
    __syncthreads();

    int gl = tid >> 5, lane = tid & 31;
    int b = half * 256 + tid;
    unsigned long long acc[5] = {0ull, 0ull, 0ull, 0ull, 0ull};

    #pragma unroll 4
    for (int hh = 0; hh < OCH; hh++) {
        unsigned w = ws[hh * 8 + gl];
        unsigned bfbits = ((w >> lane) & 1u) ? 0x3f800000u : 0u;
        unsigned long long bfp = (unsigned long long)bfbits |
                                 ((unsigned long long)bfbits << 32);
        const unsigned long long* ocp =
            reinterpret_cast<const unsigned long long*>(&ocs[hh * CLASSES]);
        #pragma unroll
        for (int i = 0; i < 5; i++) {
            unsigned long long o = ocp[i];
            asm("fma.rn.f32x2 %0, %1, %2, %0;" : "+l"(acc[i]) : "l"(bfp), "l"(o));
        }
    }
    float* dst = partLayer + ((size_t)chunk * BATCH + b) * CLASSES;
    #pragma unroll
    for (int i = 0; i < 5; i++) {
        dst[2 * i + 0] = __uint_as_float((unsigned)(acc[i] & 0xFFFFFFFFull));
        dst[2 * i + 1] = __uint_as_float((unsigned)(acc[i] >> 32));
    }
}

// ---------------- 4b) reduce + argmax + zero counts ----------------
__global__ __launch_bounds__(320) void outfinal_kernel(
    const float* __restrict__ part, float* __restrict__ preds_out,
    float* __restrict__ outact_out, int* __restrict__ cnt)
{
    int b = blockIdx.x;
    int t = threadIdx.x;                // 10 warps, one per class
    if (t < 96) cnt[b * 96 + t] = 0;    // 512*96 = 6*HID
    int w = t >> 5, l = t & 31;
    __shared__ float fin[CLASSES];
    float s = 0.f;
    #pragma unroll
    for (int i = 0; i < 6; i++) {
        int ch = l + i * 32;
        s += part[((size_t)ch * BATCH + b) * CLASSES + w];
    }
    #pragma unroll
    for (int off = 16; off > 0; off >>= 1)
        s += __shfl_down_sync(0xFFFFFFFFu, s, off);
    if (l == 0) {
        fin[w] = s;
        outact_out[b * CLASSES + w] = s;
    }
    __syncthreads();
    if (t == 0) {
        int bi = 0;
        float bv = fin[0];
        #pragma unroll
        for (int c = 1; c < CLASSES; c++)
            if (fin[c] > bv) { bv = fin[c]; bi = c; }
        preds_out[b] = (float)bi;
    }
}

// ---------------- host ----------------
static cudaStream_t s_side = nullptr;
static cudaEvent_t  s_evFork = nullptr, s_evW1 = nullptr, s_evA = nullptr;

extern "C" void kernel_launch(void* const* d_in, const int* in_sizes, int n_in,
                              void* d_out, int out_size)
{
    const float* x       = (const float*)d_in[1];
    const float* W0      = (const float*)d_in[2];
    const float* W1      = (const float*)d_in[3];
    const float* W2      = (const float*)d_in[4];
    const float* outConn = (const float*)d_in[5];

    if (!s_side) {
        cudaStreamCreateWithFlags(&s_side, cudaStreamNonBlocking);
        cudaEventCreateWithFlags(&s_evFork, cudaEventDisableTiming);
        cudaEventCreateWithFlags(&s_evW1, cudaEventDisableTiming);
        cudaEventCreateWithFlags(&s_evA, cudaEventDisableTiming);
    }

    void *ent0, *ent1, *ent2, *cnt;
    void *cp0, *ns0, *cp1, *ns1, *cp2, *ns2;
    void *act0, *act1, *act2, *act3, *part, *sink;
    cudaGetSymbolAddress(&ent0, g_ent0);  cudaGetSymbolAddress(&ent1, g_ent1);
    cudaGetSymbolAddress(&ent2, g_ent2);  cudaGetSymbolAddress(&cnt,  g_cnt);
    cudaGetSymbolAddress(&cp0, g_cp0);    cudaGetSymbolAddress(&ns0, g_ns0);
    cudaGetSymbolAddress(&cp1, g_cp1);    cudaGetSymbolAddress(&ns1, g_ns1);
    cudaGetSymbolAddress(&cp2, g_cp2);    cudaGetSymbolAddress(&ns2, g_ns2);
    cudaGetSymbolAddress(&act0, g_act0);  cudaGetSymbolAddress(&act1, g_act1);
    cudaGetSymbolAddress(&act2, g_act2);  cudaGetSymbolAddress(&act3, g_act3);
    cudaGetSymbolAddress(&part, g_part);  cudaGetSymbolAddress(&sink, g_sink);

    int* pc0 = (int*)cnt;          int* nc0 = pc0 + HID;
    int* pc1 = nc0 + HID;          int* nc1 = pc1 + HID;
    int* pc2 = nc1 + HID;          int* nc2 = pc2 + HID;

    float* preds_dst;
    float* outact_dst;
    if (out_size == BATCH * CLASSES + BATCH) {
        preds_dst  = (float*)d_out;
        outact_dst = (float*)d_out + BATCH;
    } else if (out_size == BATCH * CLASSES) {
        preds_dst  = (float*)sink;
        outact_dst = (float*)d_out;
    } else if (out_size == BATCH) {
        preds_dst  = (float*)d_out;
        outact_dst = (float*)sink;
    } else {
        preds_dst  = (float*)d_out;
        outact_dst = (float*)d_out + BATCH;
    }

    const int XGRID = 1184;
    dim3 lgrid(HID / 256, NGRP);
    dim3 ogrid(64, 2);
    const int LPART = 64 * BATCH * CLASSES;

    // ---- main: big sweeps W1, W2 ----
    cudaEventRecord(s_evFork, 0);
    cudaStreamWaitEvent(s_side, s_evFork, 0);

    extract_kernel<<<XGRID, 256>>>((const float4*)W1, 11, HID * (HID / 4),
                                   (unsigned short*)ent1, pc1, nc1);
    cudaEventRecord(s_evW1, 0);
    extract_kernel<<<XGRID, 256>>>((const float4*)W2, 11, HID * (HID / 4),
                                   (unsigned short*)ent2, pc2, nc2);
    pad_kernel<<<HID / 256, 256>>>(pc2, nc2, HID, (unsigned short*)ent2,
                                   (int*)cp2, (int*)ns2);

    // ---- side: encode, W0 chain, then layer1/outparts under W2's shadow ----
    encode_kernel<<<NGRP, 256, 0, s_side>>>(x, (unsigned*)act0);
    extract_kernel<<<XGRID, 256, 0, s_side>>>((const float4*)W0, 9, HID * (ENC / 4),
                                              (unsigned short*)ent0, pc0, nc0);
    pad_kernel<<<HID / 256, 256, 0, s_side>>>(pc0, nc0, ENC, (unsigned short*)ent0,
                                              (int*)cp0, (int*)ns0);
    layer_kernel<ENC><<<lgrid, 256, 0, s_side>>>((unsigned*)ent0, (int*)cp0,
                                                 (int*)ns0, (unsigned*)act0,
                                                 (unsigned*)act1);
    outpart_kernel<<<ogrid, 256, 0, s_side>>>((unsigned*)act1, outConn,
                                              (float*)part);
    cudaStreamWaitEvent(s_side, s_evW1, 0);
    pad_kernel<<<HID / 256, 256, 0, s_side>>>(pc1, nc1, HID, (unsigned short*)ent1,
                                              (int*)cp1, (int*)ns1);
    layer_kernel<HID><<<lgrid, 256, 0, s_side>>>((unsigned*)ent1, (int*)cp1,
                                                 (int*)ns1, (unsigned*)act1,
                                                 (unsigned*)act2);
    outpart_kernel<<<ogrid, 256, 0, s_side>>>((unsigned*)act2,
                                              outConn + (size_t)HID * CLASSES,
                                              (float*)part + LPART);
    cudaEventRecord(s_evA, s_side);

    // ---- main tail ----
    cudaStreamWaitEvent(0, s_evA, 0);
    layer_kernel<HID><<<lgrid, 256>>>((unsigned*)ent2, (int*)cp2, (int*)ns2,
                                      (unsigned*)act2, (unsigned*)act3);
    outpart_kernel<<<ogrid, 256>>>((unsigned*)act3,
                                   outConn + (size_t)2 * HID * CLASSES,
                                   (float*)part + 2 * LPART);
    outfinal_kernel<<<BATCH, 320>>>((float*)part, preds_dst, outact_dst, (int*)cnt);
}

// round 9
// speedup vs baseline: 1.1890x; 1.1890x over previous
#include <cuda_runtime.h>
#include <cuda_bf16.h>

// EISANI sparse ternary net. B=512, F=128, NUM_BITS=16, E=2048, H=8192, C=10.
// R9: R5 schedule + R5 extraction (known-good 153.8us) with ONLY the layer
// kernel upgraded: Harley-Seal CSA bit-slice accumulation, paired u32 entry
// reads (ESLOT layout), pad-to-8.

#define HID 8192
#define ENC 2048
#define BATCH 512
#define NGRP 16
#define CAP 96
#define CLASSES 10
#define OCH 128
#define NCHUNK (3 * HID / OCH)      // 192

// entry slot j of row h lives at u16 address ((j>>1)*2*HID + 2*h + (j&1));
// u32 view index (j>>1)*HID + h holds entries j (lo) and j+1 (hi).
#define ESLOT(j, h) ((((j) >> 1) * 2 * HID) + 2 * (h) + ((j) & 1))

// ---------------- scratch ----------------
__device__ unsigned short g_ent0[CAP * HID];
__device__ unsigned short g_ent1[CAP * HID];
__device__ unsigned short g_ent2[CAP * HID];
__device__ int g_cnt[6 * HID];      // pc0,nc0,pc1,nc1,pc2,nc2 (zeroed by outfinal)
__device__ int g_cp0[HID], g_ns0[HID];
__device__ int g_cp1[HID], g_ns1[HID];
__device__ int g_cp2[HID], g_ns2[HID];
__device__ unsigned g_act0[NGRP * ENC];
__device__ unsigned g_act1[NGRP * HID];
__device__ unsigned g_act2[NGRP * HID];
__device__ unsigned g_act3[NGRP * HID];
__device__ float    g_part[NCHUNK * BATCH * CLASSES];
__device__ float    g_sink[BATCH * CLASSES + BATCH];

// ---------------- 1) extraction: streaming MLP=4, atomic append (R5) --------
__global__ __launch_bounds__(256) void extract_kernel(
    const float4* __restrict__ W, int f4shf, int total_f4,
    unsigned short* __restrict__ entT, int* __restrict__ pc, int* __restrict__ nc)
{
    int t  = blockIdx.x * blockDim.x + threadIdx.x;
    int NT = gridDim.x * blockDim.x;
    int f4mask = (1 << f4shf) - 1;

    for (int base = 0; base < total_f4; base += NT * 4) {
        float4 v[4];
        int idx[4];
        #pragma unroll
        for (int j = 0; j < 4; j++) {
            idx[j] = base + t + j * NT;
            if (idx[j] < total_f4) v[j] = __ldcs(W + idx[j]);
            else                   v[j] = make_float4(0.f, 0.f, 0.f, 0.f);
        }
        #pragma unroll
        for (int j = 0; j < 4; j++) {
            float f0 = v[j].x, f1 = v[j].y, f2 = v[j].z, f3 = v[j].w;
            int cntp = (f0 > 0.f) + (f1 > 0.f) + (f2 > 0.f) + (f3 > 0.f);
            int cntn = (f0 < 0.f) + (f1 < 0.f) + (f2 < 0.f) + (f3 < 0.f);
            if ((cntp | cntn) == 0) continue;
            int row  = idx[j] >> f4shf;
            int col4 = (idx[j] & f4mask) << 2;
            if (cntp) {
                int bp = atomicAdd(&pc[row], cntp);
                float ff[4] = {f0, f1, f2, f3};
                #pragma unroll
                for (int k = 0; k < 4; k++) {
                    if (ff[k] > 0.f) {
                        if (bp < CAP) entT[ESLOT(bp, row)] = (unsigned short)(col4 + k);
                        bp++;
                    }
                }
            }
            if (cntn) {
                int bn = atomicAdd(&nc[row], cntn);
                float ff[4] = {f0, f1, f2, f3};
                #pragma unroll
                for (int k = 0; k < 4; k++) {
                    if (ff[k] < 0.f) {
                        int sl = CAP - 1 - bn;
                        if (sl >= 0) entT[ESLOT(sl, row)] = (unsigned short)(col4 + k);
                        bn++;
                    }
                }
            }
        }
    }
}

// ---------------- pad: round counts to mult of 8 with sentinels -------------
__device__ __forceinline__ void pad_row(int row, const int* pc, const int* nc,
                                        int P, unsigned short* entT,
                                        int* cp8, int* ns8)
{
    int cp = min(pc[row], 48);
    int cn = min(nc[row], 48);
    int cpp = (cp + 7) & ~7;
    for (int j = cp; j < cpp; j++) entT[ESLOT(j, row)] = (unsigned short)P;
    int ns  = CAP - cn;
    int nsp = ns & ~7;
    for (int j = nsp; j < ns; j++) entT[ESLOT(j, row)] = (unsigned short)P;
    cp8[row] = cpp;
    ns8[row] = nsp;
}

__global__ void pad_kernel(const int* __restrict__ pc, const int* __restrict__ nc,
                           int P, unsigned short* __restrict__ entT,
                           int* __restrict__ cp8, int* __restrict__ ns8)
{
    int row = blockIdx.x * blockDim.x + threadIdx.x;
    if (row < HID) pad_row(row, pc, nc, P, entT, cp8, ns8);
}

__global__ void pad2_kernel(
    const int* __restrict__ pcA, const int* __restrict__ ncA,
    unsigned short* __restrict__ eA, int* __restrict__ cpA, int* __restrict__ nsA,
    const int* __restrict__ pcB, const int* __restrict__ ncB,
    unsigned short* __restrict__ eB, int* __restrict__ cpB, int* __restrict__ nsB)
{
    int row = blockIdx.x * blockDim.x + threadIdx.x;
    if (row >= HID) return;
    if (blockIdx.y == 0) pad_row(row, pcA, ncA, HID, eA, cpA, nsA);
    else                 pad_row(row, pcB, ncB, HID, eB, cpB, nsB);
}

// ---------------- 2) thermometer encode ----------------
__global__ __launch_bounds__(256) void encode_kernel(
    const float* __restrict__ x, unsigned* __restrict__ act0T)
{
    __shared__ float xs[32 * 129];
    int g = blockIdx.x;
    int tid = threadIdx.x;
    const float* xg = x + (size_t)g * 32 * 128;
    for (int i = tid; i < 4096; i += 256)
        xs[(i >> 7) * 129 + (i & 127)] = xg[i];
    __syncthreads();
    int w = tid >> 5, lane = tid & 31;
    for (int f = w; f < 128; f += 8) {
        float xv = xs[lane * 129 + f] * 16.0f;
        unsigned myword = 0;
        #pragma unroll
        for (int j = 0; j < 16; j++) {
            unsigned m = __ballot_sync(0xFFFFFFFFu, xv > (float)j);
            if (lane == j) myword = m;
        }
        if (lane < 16) act0T[g * ENC + f * 16 + lane] = myword;
    }
}

// ---------------- 3) bit-sliced layer (Harley-Seal CSA planes) --------------
__device__ __forceinline__ void csa(unsigned& c, unsigned& s, unsigned a, unsigned b)
{
    unsigned t = s ^ a;
    c = (s & a) | (t & b);
    s = t ^ b;
}

__device__ __forceinline__ void hs8(unsigned (&pl)[6],
    unsigned v0, unsigned v1, unsigned v2, unsigned v3,
    unsigned v4, unsigned v5, unsigned v6, unsigned v7)
{
    unsigned a1, a2, a3, a4, b1, b2, c1;
    csa(a1, pl[0], v0, v1);
    csa(a2, pl[0], v2, v3);
    csa(a3, pl[0], v4, v5);
    csa(a4, pl[0], v6, v7);
    csa(b1, pl[1], a1, a2);
    csa(b2, pl[1], a3, a4);
    csa(c1, pl[2], b1, b2);
    unsigned t0 = pl[3] & c1; pl[3] ^= c1;
    unsigned t1 = pl[4] & t0; pl[4] ^= t0;
    pl[5] ^= t1;
}

template <int KDIM>
__global__ __launch_bounds__(256) void layer_kernel(
    const unsigned* __restrict__ entP,      // paired u32 view
    const int* __restrict__ cp8, const int* __restrict__ ns8,
    const unsigned* __restrict__ actInT,
    unsigned* __restrict__ actOutT)
{
    __shared__ unsigned slice[KDIM + 4];
    int tid = threadIdx.x;
    int h = blockIdx.x * 256 + tid;
    int g = blockIdx.y;
    const uint4* src4 = reinterpret_cast<const uint4*>(actInT + (size_t)g * KDIM);
    uint4* dst4 = reinterpret_cast<uint4*>(slice);
    for (int i = tid; i < KDIM / 4; i += 256) dst4[i] = src4[i];
    if (tid == 0) slice[KDIM] = 0u;    // sentinel for padded entries
    __syncthreads();

    int cp = cp8[h];
    int ns = ns8[h];
    unsigned p[6] = {0, 0, 0, 0, 0, 0};
    unsigned n[6] = {0, 0, 0, 0, 0, 0};
    const unsigned* ep = entP + h;

    #pragma unroll 1
    for (int j = 0; j < cp; j += 8) {
        int jj = j >> 1;
        unsigned e0 = ep[(jj + 0) * HID], e1 = ep[(jj + 1) * HID];
        unsigned e2 = ep[(jj + 2) * HID], e3 = ep[(jj + 3) * HID];
        hs8(p, slice[e0 & 0xFFFF], slice[e0 >> 16],
               slice[e1 & 0xFFFF], slice[e1 >> 16],
               slice[e2 & 0xFFFF], slice[e2 >> 16],
               slice[e3 & 0xFFFF], slice[e3 >> 16]);
    }
    #pragma unroll 1
    for (int j = ns; j < CAP; j += 8) {
        int jj = j >> 1;
        unsigned e0 = ep[(jj + 0) * HID], e1 = ep[(jj + 1) * HID];
        unsigned e2 = ep[(jj + 2) * HID], e3 = ep[(jj + 3) * HID];
        hs8(n, slice[e0 & 0xFFFF], slice[e0 >> 16],
               slice[e1 & 0xFFFF], slice[e1 >> 16],
               slice[e2 & 0xFFFF], slice[e2 >> 16],
               slice[e3 & 0xFFFF], slice[e3 >> 16]);
    }

    // S = P + ~N (6-bit); z = P - N >= 4 <=> S >= 67 (1000011b)
    unsigned s[7], carry = 0;
    #pragma unroll
    for (int i = 0; i < 6; i++) {
        unsigned q = ~n[i];
        unsigned x1 = p[i] ^ q;
        s[i] = x1 ^ carry;
        carry = (p[i] & q) | (carry & x1);
    }
    s[6] = carry;
    unsigned gt = 0, eq = 0xFFFFFFFFu;
    eq &= s[6];
    #pragma unroll
    for (int i = 5; i >= 2; i--) { gt |= eq & s[i]; eq &= ~s[i]; }
    eq &= s[1];
    eq &= s[0];
    actOutT[(size_t)g * HID + h] = gt | eq;
}

// ---------------- 4a) output partials (R5 fused 3-layer form) ---------------
__global__ __launch_bounds__(256) void outpart_kernel(
    const unsigned* __restrict__ a1, const unsigned* __restrict__ a2,
    const unsigned* __restrict__ a3, const float* __restrict__ outConn,
    float* __restrict__ part)
{
    __shared__ float    ocs[OCH * CLASSES];
    __shared__ unsigned ws[OCH * 8];
    int chunk = blockIdx.x;
    int half  = blockIdx.y;
    int layer = chunk >> 6;
    int hbase = (chunk & 63) * OCH;
    const unsigned* act = (layer == 0) ? a1 : (layer == 1) ? a2 : a3;
    const float* oc = outConn + ((size_t)layer * HID + hbase) * CLASSES;
    int tid = threadIdx.x;
    for (int i = tid; i < OCH * CLASSES; i += 256) ocs[i] = oc[i];
    for (int i = tid; i < OCH * 8; i += 256) {
        int hh = i >> 3, gl = i & 7;
        ws[i] = act[(size_t)(half * 8 + gl) * HID + hbase + hh];
    }
    __syncthreads();

    int gl = tid >> 5, lane = tid & 31;
    int b = half * 256 + tid;
    unsigned long long acc[5] = {0ull, 0ull, 0ull, 0ull, 0ull};

    #pragma unroll 4
    for (int hh = 0; hh < OCH; hh++) {
        unsigned w = ws[hh * 8 + gl];
        unsigned bfbits = ((w >> lane) & 1u) ? 0x3f800000u : 0u;
        unsigned long long bfp = (unsigned long long)bfbits |
                                 ((unsigned long long)bfbits << 32);
        const unsigned long long* ocp =
            reinterpret_cast<const unsigned long long*>(&ocs[hh * CLASSES]);
        #pragma unroll
        for (int i = 0; i < 5; i++) {
            unsigned long long o = ocp[i];
            asm("fma.rn.f32x2 %0, %1, %2, %0;" : "+l"(acc[i]) : "l"(bfp), "l"(o));
        }
    }
    float* dst = part + ((size_t)chunk * BATCH + b) * CLASSES;
    #pragma unroll
    for (int i = 0; i < 5; i++) {
        dst[2 * i + 0] = __uint_as_float((unsigned)(acc[i] & 0xFFFFFFFFull));
        dst[2 * i + 1] = __uint_as_float((unsigned)(acc[i] >> 32));
    }
}

// ---------------- 4b) reduce + argmax + zero counts ----------------
__global__ __launch_bounds__(320) void outfinal_kernel(
    const float* __restrict__ part, float* __restrict__ preds_out,
    float* __restrict__ outact_out, int* __restrict__ cnt)
{
    int b = blockIdx.x;
    int t = threadIdx.x;                // 10 warps, one per class
    if (t < 96) cnt[b * 96 + t] = 0;    // 512*96 = 6*HID
    int w = t >> 5, l = t & 31;
    __shared__ float fin[CLASSES];
    float s = 0.f;
    #pragma unroll
    for (int i = 0; i < 6; i++) {
        int ch = l + i * 32;
        s += part[((size_t)ch * BATCH + b) * CLASSES + w];
    }
    #pragma unroll
    for (int off = 16; off > 0; off >>= 1)
        s += __shfl_down_sync(0xFFFFFFFFu, s, off);
    if (l == 0) {
        fin[w] = s;
        outact_out[b * CLASSES + w] = s;
    }
    __syncthreads();
    if (t == 0) {
        int bi = 0;
        float bv = fin[0];
        #pragma unroll
        for (int c = 1; c < CLASSES; c++)
            if (fin[c] > bv) { bv = fin[c]; bi = c; }
        preds_out[b] = (float)bi;
    }
}

// ---------------- host (exact R5 schedule) ----------------
static cudaStream_t s_side = nullptr;
static cudaEvent_t  s_evFork = nullptr, s_evJoin = nullptr;

extern "C" void kernel_launch(void* const* d_in, const int* in_sizes, int n_in,
                              void* d_out, int out_size)
{
    const float* x       = (const float*)d_in[1];
    const float* W0      = (const float*)d_in[2];
    const float* W1      = (const float*)d_in[3];
    const float* W2      = (const float*)d_in[4];
    const float* outConn = (const float*)d_in[5];

    if (!s_side) {
        cudaStreamCreateWithFlags(&s_side, cudaStreamNonBlocking);
        cudaEventCreateWithFlags(&s_evFork, cudaEventDisableTiming);
        cudaEventCreateWithFlags(&s_evJoin, cudaEventDisableTiming);
    }

    void *ent0, *ent1, *ent2, *cnt;
    void *cp0, *ns0, *cp1, *ns1, *cp2, *ns2;
    void *act0, *act1, *act2, *act3, *part, *sink;
    cudaGetSymbolAddress(&ent0, g_ent0);  cudaGetSymbolAddress(&ent1, g_ent1);
    cudaGetSymbolAddress(&ent2, g_ent2);  cudaGetSymbolAddress(&cnt,  g_cnt);
    cudaGetSymbolAddress(&cp0, g_cp0);    cudaGetSymbolAddress(&ns0, g_ns0);
    cudaGetSymbolAddress(&cp1, g_cp1);    cudaGetSymbolAddress(&ns1, g_ns1);
    cudaGetSymbolAddress(&cp2, g_cp2);    cudaGetSymbolAddress(&ns2, g_ns2);
    cudaGetSymbolAddress(&act0, g_act0);  cudaGetSymbolAddress(&act1, g_act1);
    cudaGetSymbolAddress(&act2, g_act2);  cudaGetSymbolAddress(&act3, g_act3);
    cudaGetSymbolAddress(&part, g_part);  cudaGetSymbolAddress(&sink, g_sink);

    int* pc0 = (int*)cnt;          int* nc0 = pc0 + HID;
    int* pc1 = nc0 + HID;          int* nc1 = pc1 + HID;
    int* pc2 = nc1 + HID;          int* nc2 = pc2 + HID;

    float* preds_dst;
    float* outact_dst;
    if (out_size == BATCH * CLASSES + BATCH) {
        preds_dst  = (float*)d_out;
        outact_dst = (float*)d_out + BATCH;
    } else if (out_size == BATCH * CLASSES) {
        preds_dst  = (float*)sink;
        outact_dst = (float*)d_out;
    } else if (out_size == BATCH) {
        preds_dst  = (float*)d_out;
        outact_dst = (float*)sink;
    } else {
        preds_dst  = (float*)d_out;
        outact_dst = (float*)d_out + BATCH;
    }

    const int XGRID = 1184;
    dim3 lgrid(HID / 256, NGRP);

    // ---- fork side chain ----
    cudaEventRecord(s_evFork, 0);
    cudaStreamWaitEvent(s_side, s_evFork, 0);

    encode_kernel<<<NGRP, 256, 0, s_side>>>(x, (unsigned*)act0);
    extract_kernel<<<XGRID, 256, 0, s_side>>>((const float4*)W0, 9, HID * (ENC / 4),
                                              (unsigned short*)ent0, pc0, nc0);
    pad_kernel<<<HID / 256, 256, 0, s_side>>>(pc0, nc0, ENC, (unsigned short*)ent0,
                                              (int*)cp0, (int*)ns0);
    layer_kernel<ENC><<<lgrid, 256, 0, s_side>>>((unsigned*)ent0, (int*)cp0,
                                                 (int*)ns0, (unsigned*)act0,
                                                 (unsigned*)act1);
    cudaEventRecord(s_evJoin, s_side);

    // ---- main chain: the two big HBM sweeps ----
    extract_kernel<<<XGRID, 256>>>((const float4*)W1, 11, HID * (HID / 4),
                                   (unsigned short*)ent1, pc1, nc1);
    extract_kernel<<<XGRID, 256>>>((const float4*)W2, 11, HID * (HID / 4),
                                   (unsigned short*)ent2, pc2, nc2);
    dim3 pgrid(HID / 256, 2);
    pad2_kernel<<<pgrid, 256>>>(pc1, nc1, (unsigned short*)ent1, (int*)cp1, (int*)ns1,
                                pc2, nc2, (unsigned short*)ent2, (int*)cp2, (int*)ns2);

    cudaStreamWaitEvent(0, s_evJoin, 0);

    layer_kernel<HID><<<lgrid, 256>>>((unsigned*)ent1, (int*)cp1, (int*)ns1,
                                      (unsigned*)act1, (unsigned*)act2);
    layer_kernel<HID><<<lgrid, 256>>>((unsigned*)ent2, (int*)cp2, (int*)ns2,
                                      (unsigned*)act2, (unsigned*)act3);

    dim3 ogrid(NCHUNK, 2);
    outpart_kernel<<<ogrid, 256>>>((unsigned*)act1, (unsigned*)act2, (unsigned*)act3,
                                   outConn, (float*)part);
    outfinal_kernel<<<BATCH, 320>>>((float*)part, preds_dst, outact_dst, (int*)cnt);
}